// round 11
// baseline (speedup 1.0000x reference)
#include <cuda_runtime.h>
#include <math.h>

#define NN 100000
#define NE 1200000
#define KP1 4096
#define KP2 256
#define SLOPE 0.01f
#define EC 65536
#define NB 148
#define NT 256
#define NTH (NB*NT)
#define NCH 98            // ceil(NN/1024), chunk=1024

// ---------------- scratch (no allocations) ----------------
__device__ int      g_degi[NN];
__device__ double   g_ddinv[NN];
__device__ double   g_dagg3[NN * 3];       // aliased later as x2 floats
__device__ unsigned g_keys1[NN];
__device__ int      g_inv1[NN];
__device__ float    g_B[524288];           // [x1p | agg64]
__device__ float    g_C[524288];           // agg128

#define G_X2     ((float*)g_dagg3)         /* [KP1*128] after dagg3 dead */
#define G_X1P    (g_B)
#define G_AGG64  (g_B + 262144)
#define G_AGG128 (g_C)

__device__ unsigned g_hist[256];
__device__ unsigned g_prefix;
__device__ int      g_kst;
__device__ int      g_cg[NCH], g_ce[NCH], g_ceOff[NCH], g_keptOff[NCH];
__device__ int      g_sel1[KP1], g_sel1s[KP1];
__device__ unsigned long long g_ck[KP1];
__device__ int      g_rank[KP1];
__device__ int2     g_edge[EC];
__device__ int      g_ne1;
__device__ float    g_dinv2[KP1];
__device__ float    g_sc2[KP1];
__device__ int      g_win[KP2];
__device__ float    g_xflat[KP2 * 256];
__device__ float    g_invp1;
__device__ double   g_invp2d;
__device__ unsigned g_barc, g_barg;        // zero-init; self-resetting

__device__ __forceinline__ float leaky(float v) { return v > 0.f ? v : SLOPE * v; }
__device__ __forceinline__ unsigned fkey(float f) {
    unsigned u = __float_as_uint(f);
    return (u & 0x80000000u) ? ~u : (u | 0x80000000u);
}
__device__ __forceinline__ float ikey(unsigned k) {
    return __uint_as_float((k & 0x80000000u) ? (k ^ 0x80000000u) : ~k);
}

// software grid barrier: all NB blocks resident (NB == #SMs) -> no deadlock.
__device__ __forceinline__ void gridbar() {
    __syncthreads();
    if (threadIdx.x == 0) {
        unsigned gen = atomicAdd(&g_barg, 0u);
        __threadfence();
        if (atomicAdd(&g_barc, 1u) == NB - 1u) {
            atomicExch(&g_barc, 0u);
            __threadfence();
            atomicAdd(&g_barg, 1u);
        } else {
            while (atomicAdd(&g_barg, 0u) == gen) __nanosleep(64);
        }
        __threadfence();
    }
    __syncthreads();
}

// ---------------- 1) setup ----------------
__global__ void k_setup(const float* __restrict__ p1, const float* __restrict__ p2,
                        const float* __restrict__ fcb, float* __restrict__ out) {
    int gid = blockIdx.x * NT + threadIdx.x;
    for (int i = gid; i < NN; i += NTH) g_degi[i] = 0;
    for (int i = gid; i < NN * 3; i += NTH) g_dagg3[i] = 0.0;
    for (int i = gid; i < KP1; i += NTH) g_dinv2[i] = 0.f;
    for (int i = gid; i < 524288; i += NTH) g_C[i] = 0.f;
    for (int i = gid; i < 262144; i += NTH) g_B[262144 + i] = 0.f;
    if (gid < 256) g_hist[gid] = 0;
    if (gid < 512) out[gid] = fcb[gid];
    if (gid == 0) {
        g_ne1 = 0;
        double s = 0.0;
        for (int i = 0; i < 64; i++) { double v = (double)p1[i]; s += v * v; }
        g_invp1 = (float)(1.0 / sqrt(s));
        double s2 = 0.0;
        for (int i = 0; i < 256; i++) { double v = (double)p2[i]; s2 += v * v; }
        g_invp2d = 1.0 / sqrt(s2);
    }
}

// ---------------- 2) conv1: deg | dinv | agg3 | score1 ----------------
__global__ void k_conv1(const int* __restrict__ src, const int* __restrict__ dst,
                        const float* __restrict__ pos, const float* __restrict__ W1,
                        const float* __restrict__ b1, const float* __restrict__ p1) {
    int t = threadIdx.x, gid = blockIdx.x * NT + t;
    for (int e = gid; e < NE; e += NTH) atomicAdd(&g_degi[dst[e]], 1);
    gridbar();
    for (int i = gid; i < NN; i += NTH) g_ddinv[i] = 1.0 / sqrt((double)g_degi[i] + 1.0);
    gridbar();
    for (int e = gid; e < NE; e += NTH) {       // accumulate pos[s]*dinv[s]; dinv[d] applied later
        int s = src[e], d = dst[e];
        double ds = g_ddinv[s];
        atomicAdd(&g_dagg3[d * 3 + 0], (double)pos[s * 3 + 0] * ds);
        atomicAdd(&g_dagg3[d * 3 + 1], (double)pos[s * 3 + 1] * ds);
        atomicAdd(&g_dagg3[d * 3 + 2], (double)pos[s * 3 + 2] * ds);
    }
    gridbar();
    __shared__ float sW[192], sb[64], sp[64];
    if (t < 192) sW[t] = W1[t];
    if (t < 64) { sb[t] = b1[t]; sp[t] = p1[t]; }
    __syncthreads();
    float ip1 = g_invp1;
    for (int i = gid; i < NN; i += NTH) {
        double dd = g_ddinv[i], d2 = dd * dd;
        float c0 = (float)(g_dagg3[3 * i + 0] * dd + (double)pos[3 * i + 0] * d2);
        float c1 = (float)(g_dagg3[3 * i + 1] * dd + (double)pos[3 * i + 1] * d2);
        float c2 = (float)(g_dagg3[3 * i + 2] * dd + (double)pos[3 * i + 2] * d2);
        float s = 0.f;
#pragma unroll
        for (int f = 0; f < 64; f++) {
            float v = sb[f] + c0 * sW[f] + c1 * sW[64 + f] + c2 * sW[128 + f];
            s += leaky(v) * sp[f];
        }
        g_keys1[i] = fkey(tanhf(s * ip1));
    }
}

// ---------------- 3) pool1 mega: radix select, compact, rank, x1p, filter, conv2 agg, x2, agg128 ----------------
__global__ void k_pool1(const int* __restrict__ src, const int* __restrict__ dst,
                        const float* __restrict__ pos, const float* __restrict__ W1,
                        const float* __restrict__ b1, const float* __restrict__ W2,
                        const float* __restrict__ b2) {
    int t = threadIdx.x, gid = blockIdx.x * NT + t;
    int lane = t & 31, wid = t >> 5;
    __shared__ unsigned sh_h[256];
    __shared__ int sw[8], swo[8];
    __shared__ int sg, se;
    __shared__ float sW2[64 * 128];
    __shared__ float shx[16 * 64];
    __shared__ float sb2[128];
    __shared__ unsigned long long sj[256];

    // ---- radix select: 4 rounds of 8 bits ----
#pragma unroll 1
    for (int round = 0; round < 4; round++) {
        int shift = 24 - 8 * round;
        sh_h[t] = 0;
        __syncthreads();
        unsigned pr = (round == 0) ? 0u : __ldcg(&g_prefix);
        for (int i = gid; i < NN; i += NTH) {
            unsigned key = g_keys1[i];
            if (round == 0 || (key >> (shift + 8)) == pr)
                atomicAdd(&sh_h[(key >> shift) & 255u], 1u);
        }
        __syncthreads();
        if (sh_h[t]) atomicAdd(&g_hist[t], sh_h[t]);
        gridbar();
        if (blockIdx.x == 0) {       // parallel select via suffix-scan
            int k = (round == 0) ? KP1 : __ldcg(&g_kst);
            sh_h[t] = atomicAdd(&g_hist[t], 0u);
            g_hist[t] = 0;
            __syncthreads();
            for (int off = 1; off < 256; off <<= 1) {
                unsigned add = (t + off < 256) ? sh_h[t + off] : 0u;
                __syncthreads();
                sh_h[t] += add;
                __syncthreads();
            }
            // sh_h[t] = suffix count of bins >= t
            unsigned nxt = (t == 255) ? 0u : sh_h[t + 1];
            if (sh_h[t] >= (unsigned)k && nxt < (unsigned)k) {
                unsigned np = (round == 0) ? (unsigned)t
                                           : ((__ldcg(&g_prefix) << 8) | (unsigned)t);
                atomicExch(&g_prefix, np);
                atomicExch((unsigned*)&g_kst, (unsigned)(k - (int)nxt));
            }
        }
        gridbar();
    }
    unsigned th = __ldcg(&g_prefix);
    int T = (int)__ldcg((const unsigned*)&g_kst);

    // ---- poolcnt: per-chunk (1024 nodes) gt/eq totals ----
    for (int c = blockIdx.x; c < NCH; c += NB) {
        int cgt = 0, ceq = 0;
#pragma unroll
        for (int s = 0; s < 4; s++) {
            int i = c * 1024 + s * 256 + t;
            if (i < NN) { unsigned k = g_keys1[i]; cgt += (k > th); ceq += (k == th); }
        }
#pragma unroll
        for (int o = 16; o > 0; o >>= 1) {
            cgt += __shfl_down_sync(0xffffffffu, cgt, o);
            ceq += __shfl_down_sync(0xffffffffu, ceq, o);
        }
        __syncthreads();
        if (t == 0) { sg = 0; se = 0; }
        __syncthreads();
        if (lane == 0) { atomicAdd(&sg, cgt); atomicAdd(&se, ceq); }
        __syncthreads();
        if (t == 0) { g_cg[c] = sg; g_ce[c] = se; }
    }
    gridbar();
    // ---- scan chunks (block0; parallel load, cheap serial scan in shared) ----
    if (blockIdx.x == 0) {
        int* s_cg = (int*)shx;          // 98 ints
        int* s_ce = s_cg + 128;         // 98 ints
        if (t < NCH) { s_cg[t] = __ldcg(&g_cg[t]); s_ce[t] = __ldcg(&g_ce[t]); }
        __syncthreads();
        if (t == 0) {
            int ceo = 0, ko = 0;
            for (int c = 0; c < NCH; c++) {
                g_ceOff[c] = ceo;
                int take = T - ceo; if (take < 0) take = 0; if (take > s_ce[c]) take = s_ce[c];
                g_keptOff[c] = ko;
                ko += s_cg[c] + take;
                ceo += s_ce[c];
            }
        }
    }
    gridbar();
    // ---- assign: stable index-order compaction (4 sub-rounds per 1024-chunk) ----
    for (int c = blockIdx.x; c < NCH; c += NB) {
        int ceoffc = g_ceOff[c], koffc = g_keptOff[c];
        int base_eq = 0, base_kept = 0;
#pragma unroll 1
        for (int s = 0; s < 4; s++) {
            int i = c * 1024 + s * 256 + t;
            int gt = 0, eq = 0;
            if (i < NN) { unsigned k = g_keys1[i]; gt = (k > th); eq = (k == th); }
            unsigned be = __ballot_sync(0xffffffffu, eq);
            int eqr = __popc(be & ((1u << lane) - 1u));
            __syncthreads();
            if (lane == 0) sw[wid] = __popc(be);
            __syncthreads();
            if (t == 0) { int ss = 0; for (int w = 0; w < 8; w++) { swo[w] = ss; ss += sw[w]; } sg = ss; }
            __syncthreads();
            eqr += swo[wid];
            int kept = gt || (eq && (ceoffc + base_eq + eqr) < T);
            unsigned bk = __ballot_sync(0xffffffffu, kept);
            int kr = __popc(bk & ((1u << lane) - 1u));
            __syncthreads();
            if (lane == 0) sw[wid] = __popc(bk);
            __syncthreads();
            if (t == 0) { int ss = 0; for (int w = 0; w < 8; w++) { swo[w] = ss; ss += sw[w]; } se = ss; }
            __syncthreads();
            kr += swo[wid];
            if (i < NN) {
                if (kept) g_sel1[koffc + base_kept + kr] = i;
                g_inv1[i] = -1;
            }
            __syncthreads();
            base_eq += sg; base_kept += se;
        }
    }
    gridbar();
    // ---- ck1 ----
    for (int id = gid; id < KP1; id += NTH) {
        int v = g_sel1[id];
        g_ck[id] = ((unsigned long long)g_keys1[v] << 32) | (unsigned)(0xFFFFFFFFu - (unsigned)v);
        g_rank[id] = 0;
    }
    gridbar();
    // ---- rank (pool1 exact reference order) ----
    for (int p = blockIdx.x; p < 256; p += NB) {
        int it = p & 15, jt = p >> 4;
        __syncthreads();
        sj[t] = g_ck[jt * 256 + t];
        __syncthreads();
        unsigned long long ki = g_ck[it * 256 + t];
        int cnt = 0;
#pragma unroll 8
        for (int j = 0; j < 256; j++) cnt += (sj[j] > ki);
        if (cnt) atomicAdd(&g_rank[it * 256 + t], cnt);
    }
    gridbar();
    // ---- perm1 ----
    for (int id = gid; id < KP1; id += NTH) {
        int v = g_sel1[id];
        int r = __ldcg(&g_rank[id]);
        g_sel1s[r] = v;
        g_inv1[v] = r;
    }
    gridbar();
    // ---- x1p (kept rows, scaled by score) + filter (surviving edges, deg2) ----
    for (int idx = gid; idx < KP1 * 64; idx += NTH) {
        int id = idx >> 6, f = idx & 63;
        int v = g_sel1s[id];
        double dd = g_ddinv[v], d2 = dd * dd;
        float c0 = (float)(g_dagg3[3 * v + 0] * dd + (double)pos[3 * v + 0] * d2);
        float c1 = (float)(g_dagg3[3 * v + 1] * dd + (double)pos[3 * v + 1] * d2);
        float c2 = (float)(g_dagg3[3 * v + 2] * dd + (double)pos[3 * v + 2] * d2);
        float score = ikey(g_keys1[v]);
        float val = b1[f] + c0 * W1[f] + c1 * W1[64 + f] + c2 * W1[128 + f];
        G_X1P[id * 64 + f] = leaky(val) * score;
    }
    for (int e = gid; e < NE; e += NTH) {
        int ms = g_inv1[src[e]];
        int md = g_inv1[dst[e]];
        if (ms >= 0 && md >= 0) {
            int pp = atomicAdd(&g_ne1, 1);
            if (pp < EC) g_edge[pp] = make_int2(ms, md);
            atomicAdd(&g_dinv2[md], 1.0f);
        }
    }
    gridbar();
    // ---- dinv2 ----
    for (int i = gid; i < KP1; i += NTH)
        g_dinv2[i] = 1.0f / sqrtf(g_dinv2[i] + 1.0f);
    gridbar();
    // ---- agg64 ----
    int ne = atomicAdd(&g_ne1, 0); if (ne > EC) ne = EC;
    for (int idx = gid; idx < ne * 64; idx += NTH) {
        int e = idx >> 6, f = idx & 63;
        int2 ed = g_edge[e];
        float nm = g_dinv2[ed.x] * g_dinv2[ed.y];
        atomicAdd(&G_AGG64[ed.y * 64 + f], G_X1P[ed.x * 64 + f] * nm);
    }
    gridbar();
    // ---- x2 tiles (16 nodes/tile, 256 tiles) ----
    for (int i = t; i < 64 * 128; i += NT) sW2[i] = W2[i];
    if (t < 128) sb2[t] = b2[t];
    __syncthreads();
    for (int tile = blockIdx.x; tile < 256; tile += NB) {
        int n0 = tile * 16;
        __syncthreads();
        for (int i = t; i < 16 * 64; i += NT) {
            int n = i >> 6, c = i & 63;
            int node = n0 + n;
            float d = g_dinv2[node];
            shx[i] = G_AGG64[node * 64 + c] + G_X1P[node * 64 + c] * d * d;
        }
        __syncthreads();
        int tc = t & 127, hh = t >> 7;
#pragma unroll 1
        for (int nn = 0; nn < 8; nn++) {
            int n = nn * 2 + hh;
            float acc = sb2[tc];
#pragma unroll
            for (int c = 0; c < 64; c++) acc += shx[n * 64 + c] * sW2[c * 128 + tc];
            G_X2[(n0 + n) * 128 + tc] = leaky(acc);
        }
    }
    gridbar();
    // ---- agg128 (G_X2 aliases dagg3 read earlier -> bypass L1 with __ldcg) ----
    for (int idx = gid; idx < ne * 128; idx += NTH) {
        int e = idx >> 7, f = idx & 127;
        int2 ed = g_edge[e];
        float nm = g_dinv2[ed.x] * g_dinv2[ed.y];
        atomicAdd(&G_AGG128[ed.y * 128 + f], __ldcg(&G_X2[ed.x * 128 + f]) * nm);
    }
}

// ---------------- 4) x3 + score2 + rank + gather + FC ----------------
__global__ void k_x3m(const float* __restrict__ W3, const float* __restrict__ b3,
                      const float* __restrict__ p2, const float* __restrict__ fcW,
                      float* __restrict__ out) {
    int t = threadIdx.x, gid = blockIdx.x * NT + t;
    __shared__ float sW[128 * 64];      // 32 KB
    __shared__ float sh[8 * 128];       // 4 KB
    __shared__ float sx3[8 * 256];      // 8 KB (reused as sj in rank)
    __shared__ float sb[256], sp[256];  // 2 KB
    sb[t] = b3[t]; sp[t] = p2[t];
    double ip2 = g_invp2d;
    // ---- x3 tiles + score2 ----
    for (int tile = blockIdx.x; tile < 512; tile += NB) {
        int n0 = tile * 8;
        __syncthreads();
        for (int i = t; i < 8 * 128; i += NT) {
            int n = i >> 7, c = i & 127;
            int node = n0 + n;
            float d = g_dinv2[node];
            sh[i] = G_AGG128[node * 128 + c] + G_X2[node * 128 + c] * d * d;
        }
        int cc = t & 63, ng = t >> 6;
#pragma unroll 1
        for (int wt = 0; wt < 4; wt++) {
            __syncthreads();
            for (int i = t; i < 128 * 64; i += NT) {
                int c = i >> 6, w = i & 63;
                sW[i] = W3[c * 256 + wt * 64 + w];
            }
            __syncthreads();
            int col = wt * 64 + cc;
            float bb = sb[col];
#pragma unroll
            for (int g = 0; g < 2; g++) {
                int n = ng * 2 + g;
                float acc = bb;
#pragma unroll
                for (int c = 0; c < 128; c++) acc += sh[n * 128 + c] * sW[c * 64 + cc];
                sx3[n * 256 + col] = leaky(acc);
            }
        }
        __syncthreads();
        int w = t >> 5, lane = t & 31;
        double s = 0.0;
        for (int c = lane; c < 256; c += 32) s += (double)sx3[w * 256 + c] * (double)sp[c];
#pragma unroll
        for (int o = 16; o > 0; o >>= 1) s += __shfl_down_sync(0xffffffffu, s, o);
        if (lane == 0) {
            int node = n0 + w;
            float sc = tanhf((float)(s * ip2));
            g_sc2[node] = sc;
            g_ck[node] = ((unsigned long long)fkey(sc) << 32) | (unsigned)(0xFFFFFFFFu - (unsigned)node);
            g_rank[node] = 0;
        }
    }
    gridbar();
    // ---- rank ----
    unsigned long long* sjj = (unsigned long long*)sx3;
    for (int p = blockIdx.x; p < 256; p += NB) {
        int it = p & 15, jt = p >> 4;
        __syncthreads();
        sjj[t] = g_ck[jt * 256 + t];
        __syncthreads();
        unsigned long long ki = g_ck[it * 256 + t];
        int cnt = 0;
#pragma unroll 8
        for (int j = 0; j < 256; j++) cnt += (sjj[j] > ki);
        if (cnt) atomicAdd(&g_rank[it * 256 + t], cnt);
    }
    gridbar();
    // ---- winners ----
    for (int i = gid; i < KP1; i += NTH) {
        int r = __ldcg(&g_rank[i]);
        if (r < KP2) g_win[r] = i;
    }
    gridbar();
    // ---- gather (recompute x3 rows for 256 winners) ----
    for (int r = blockIdx.x; r < KP2; r += NB) {
        __syncthreads();
        int i = g_win[r];
        if (t < 128) {
            float d = g_dinv2[i];
            sh[t] = G_AGG128[i * 128 + t] + G_X2[i * 128 + t] * d * d;
        }
        __syncthreads();
        float ssc = g_sc2[i];
        float acc = sb[t];
#pragma unroll 8
        for (int k = 0; k < 128; k++) acc += sh[k] * W3[k * 256 + t];
        g_xflat[t * 256 + r] = leaky(acc) * ssc;
    }
    gridbar();
    // ---- FC: out += xflat @ fcW (out pre-initialized with fcb in setup) ----
    const int rows_per = (65536 + NB - 1) / NB;   // 443
    int r0 = blockIdx.x * rows_per;
    int r1 = r0 + rows_per; if (r1 > 65536) r1 = 65536;
    const float2* Wp = (const float2*)fcW;
    float2 acc2 = make_float2(0.f, 0.f);
#pragma unroll 4
    for (int row = r0; row < r1; row++) {
        float v = g_xflat[row];
        float2 w = __ldg(&Wp[(size_t)row * 256 + t]);
        acc2.x += v * w.x; acc2.y += v * w.y;
    }
    atomicAdd(&out[2 * t + 0], acc2.x);
    atomicAdd(&out[2 * t + 1], acc2.y);
}

// ---------------- launch ----------------
extern "C" void kernel_launch(void* const* d_in, const int* in_sizes, int n_in,
                              void* d_out, int out_size) {
    const float* pos = (const float*)d_in[0];
    const int*   ei  = (const int*)d_in[1];      // int32 edge_index
    const float* W1  = (const float*)d_in[2];
    const float* b1  = (const float*)d_in[3];
    const float* W2  = (const float*)d_in[4];
    const float* b2  = (const float*)d_in[5];
    const float* W3  = (const float*)d_in[6];
    const float* b3  = (const float*)d_in[7];
    const float* p1  = (const float*)d_in[8];
    const float* p2  = (const float*)d_in[9];
    const float* fcW = (const float*)d_in[10];
    const float* fcb = (const float*)d_in[11];
    float* out = (float*)d_out;
    (void)n_in; (void)in_sizes; (void)out_size;

    const int* src = ei;
    const int* dst = ei + NE;

    k_setup<<<NB, NT>>>(p1, p2, fcb, out);
    k_conv1<<<NB, NT>>>(src, dst, pos, W1, b1, p1);
    k_pool1<<<NB, NT>>>(src, dst, pos, W1, b1, W2, b2);
    k_x3m<<<NB, NT>>>(W3, b3, p2, fcW, out);
}